// round 9
// baseline (speedup 1.0000x reference)
#include <cuda_runtime.h>
#include <cuda_fp16.h>
#include <cstdint>

// ============================================================================
// Problem dims: out[M,N] = scale * x[M,K] @ W[N,K]^T + bias[N]
// ============================================================================
#define KTOT 4096
#define MTOT 8192   // 4 * 2048
#define NTOT 11008

constexpr int BM = 128, BN = 160, BK = 64;
constexpr int NPAD = 11040;            // 69 * 160
constexpr int KCHUNKS = KTOT / BK;     // 64
constexpr int NTM = MTOT / BM;         // 64
constexpr int NTN = NPAD / BN;         // 69
constexpr int NSTAGE = 3;
constexpr int NTHREADS = 320;          // 10 warps: grid 2(M) x 5(N), warp tile 64x32

constexpr int A_BYTES = BM * BK * 2;            // 16384
constexpr int B_BYTES = BN * BK * 2;            // 20480
constexpr int STAGE_BYTES = A_BYTES + B_BYTES;  // 36864
constexpr int SMEM_TOTAL = NSTAGE * STAGE_BYTES;// 110592 per CTA -> 2 CTAs/SM

// ============================================================================
// Device scratch (zero-initialized; W pad rows [11008,11040) stay zero)
// ============================================================================
static __device__ __half g_xh[(size_t)MTOT * KTOT];   // 64 MB
static __device__ __half g_wh[(size_t)NPAD * KTOT];   // 90 MB

// ============================================================================
// Helpers (plain sm_103 PTX only: cp.async / ldmatrix / mma.sync)
// ============================================================================
__device__ __forceinline__ uint32_t smem_u32(const void* p) {
    return (uint32_t)__cvta_generic_to_shared(p);
}

__device__ __forceinline__ uint32_t sw128(uint32_t o) {
    return o ^ ((o >> 3) & 0x70);
}

__device__ __forceinline__ void cp16(uint32_t dst, const void* src) {
    asm volatile("cp.async.cg.shared.global [%0], [%1], 16;\n"
                 :: "r"(dst), "l"(src) : "memory");
}
#define CP_COMMIT() asm volatile("cp.async.commit_group;\n" ::: "memory")
#define CP_WAIT(N)  asm volatile("cp.async.wait_group %0;\n" :: "n"(N) : "memory")

__device__ __forceinline__ void ldsm4(uint32_t r[4], uint32_t addr) {
    asm volatile("ldmatrix.sync.aligned.m8n8.x4.shared.b16 {%0,%1,%2,%3}, [%4];"
                 : "=r"(r[0]), "=r"(r[1]), "=r"(r[2]), "=r"(r[3]) : "r"(addr));
}

__device__ __forceinline__ void mma16816(float c[4], const uint32_t a[4],
                                         uint32_t b0, uint32_t b1) {
    asm volatile(
        "mma.sync.aligned.m16n8k16.row.col.f32.f16.f16.f32 "
        "{%0,%1,%2,%3}, {%4,%5,%6,%7}, {%8,%9}, {%0,%1,%2,%3};"
        : "+f"(c[0]), "+f"(c[1]), "+f"(c[2]), "+f"(c[3])
        : "r"(a[0]), "r"(a[1]), "r"(a[2]), "r"(a[3]), "r"(b0), "r"(b1));
}

__device__ __forceinline__ uint32_t pack2(__half2 h) {
    uint32_t u;
    *reinterpret_cast<__half2*>(&u) = h;
    return u;
}

// ============================================================================
// Conversion kernels (8 elements / thread)
// ============================================================================
__global__ void __launch_bounds__(256) convert_x_kernel(const float* __restrict__ x) {
    size_t i = (size_t)blockIdx.x * 256 + threadIdx.x;
    const float4 a = reinterpret_cast<const float4*>(x)[2 * i];
    const float4 b = reinterpret_cast<const float4*>(x)[2 * i + 1];
    uint4 u;
    u.x = pack2(__floats2half2_rn(a.x, a.y));
    u.y = pack2(__floats2half2_rn(a.z, a.w));
    u.z = pack2(__floats2half2_rn(b.x, b.y));
    u.w = pack2(__floats2half2_rn(b.z, b.w));
    reinterpret_cast<uint4*>(g_xh)[i] = u;
}

__global__ void __launch_bounds__(256) convert_w_kernel(const int* __restrict__ w) {
    size_t i = (size_t)blockIdx.x * 256 + threadIdx.x;   // covers 11008*4096 ints
    const int4 a = reinterpret_cast<const int4*>(w)[2 * i];
    const int4 b = reinterpret_cast<const int4*>(w)[2 * i + 1];
    uint4 u;
    u.x = pack2(__floats2half2_rn((float)a.x, (float)a.y));
    u.y = pack2(__floats2half2_rn((float)a.z, (float)a.w));
    u.z = pack2(__floats2half2_rn((float)b.x, (float)b.y));
    u.w = pack2(__floats2half2_rn((float)b.z, (float)b.w));
    reinterpret_cast<uint4*>(g_wh)[i] = u;
}

// ============================================================================
// GEMM: 320 threads, 2 CTAs/SM (20 warps/SM). Warp grid 2(M) x 5(N),
// warp tile 64x32. CTA tile 128x160, 3-stage cp.async pipeline.
// ============================================================================
__global__ void __launch_bounds__(NTHREADS, 2)
gemm_kernel(const float* __restrict__ scale_p, const float* __restrict__ bias,
            float* __restrict__ out)
{
    extern __shared__ char smem[];
    const uint32_t sb = smem_u32(smem);
    const int tid = threadIdx.x;
    const int wid = tid >> 5;
    const int lane = tid & 31;
    const int wm = wid & 1;        // 0..1  (M)
    const int wn = wid >> 1;       // 0..4  (N)

    // CTA rasterization: group of 16 M-tiles per N column (same-SM pairs share B)
    const int GROUP = 16;
    const int tpg = GROUP * NTN;   // 1104
    const int b = blockIdx.x;
    const int g = b / tpg;
    const int rem = b - g * tpg;
    const int tm = g * GROUP + (rem & (GROUP - 1));
    const int tn = rem >> 4;

    const __half* xa = g_xh + (size_t)tm * BM * KTOT;
    const __half* wb = g_wh + (size_t)tn * BN * KTOT;

    float acc[4][4][4];            // warp tile 64x32
#pragma unroll
    for (int mt = 0; mt < 4; mt++)
#pragma unroll
        for (int nt = 0; nt < 4; nt++)
#pragma unroll
            for (int q = 0; q < 4; q++) acc[mt][nt][q] = 0.f;

    // ---- async loader: A = 1024 16B-units, B = 1280 units ----
    auto load_chunk = [&](int stage, int chunk) {
        const uint32_t st = sb + stage * STAGE_BYTES;
        const int c0 = chunk * BK;
#pragma unroll
        for (int u = tid; u < 1024; u += NTHREADS) {      // A: 128 rows x 128B
            int row = u >> 3, col = (u & 7) * 8;
            cp16(st + sw128(u * 16), xa + (size_t)row * KTOT + c0 + col);
        }
#pragma unroll
        for (int r = 0; r < 4; r++) {                     // B: 160 rows x 128B
            int u = tid + r * NTHREADS;
            int row = u >> 3, col = (u & 7) * 8;
            cp16(st + A_BYTES + sw128(u * 16), wb + (size_t)row * KTOT + c0 + col);
        }
        CP_COMMIT();
    };

    load_chunk(0, 0);
    load_chunk(1, 1);

    // fragment double buffers
    uint32_t bfb[2][2][4];    // [buf][gN][4]
    uint32_t afb[2][4];       // [buf][4]

    const uint32_t lrow = (uint32_t)(lane & 15) * 128;
    const uint32_t lk   = (uint32_t)(lane >> 4) * 16;   // bytes

    for (int i = 0; i < KCHUNKS; i++) {
        const int st = i % NSTAGE;
        if (i + 1 < KCHUNKS) { CP_WAIT(1); } else { CP_WAIT(0); }
        __syncthreads();
        if (i + 2 < KCHUNKS) load_chunk((i + 2) % NSTAGE, i + 2);

        const uint32_t abase = sb + st * STAGE_BYTES;
        const uint32_t bbase = abase + A_BYTES;

        auto ldA = [&](int buf, int ks, int mt) {
            uint32_t o = (uint32_t)(wm * 64 + mt * 16) * 128 + lrow
                       + (uint32_t)ks * 32 + lk;
            ldsm4(afb[buf], abase + sw128(o));
        };
        auto ldB = [&](int buf, int ks) {
#pragma unroll
            for (int gN = 0; gN < 2; gN++) {
                uint32_t o = (uint32_t)(wn * 32 + gN * 16) * 128 + lrow
                           + (uint32_t)ks * 32 + lk;
                ldsm4(bfb[buf][gN], bbase + sw128(o));
            }
        };

        ldB(0, 0);
        ldA(0, 0, 0);

#pragma unroll
        for (int ks = 0; ks < 4; ks++) {
            if (ks < 3) ldB((ks + 1) & 1, ks + 1);
#pragma unroll
            for (int mt = 0; mt < 4; mt++) {
                const int p = ks * 4 + mt;
                if (mt < 3)           ldA((p + 1) & 1, ks, mt + 1);
                else if (ks < 3)      ldA((p + 1) & 1, ks + 1, 0);
                const uint32_t* af = afb[p & 1];
                const uint32_t (*bf)[4] = bfb[ks & 1];
#pragma unroll
                for (int gN = 0; gN < 2; gN++) {
                    mma16816(acc[mt][2 * gN],     af, bf[gN][0], bf[gN][2]);
                    mma16816(acc[mt][2 * gN + 1], af, bf[gN][1], bf[gN][3]);
                }
            }
        }
    }

    // ---- epilogue: scale * acc + bias (guard N pad) ----
    const float s = __ldg(scale_p);
    const int r0 = lane >> 2;
    const int c0 = (lane & 3) * 2;

#pragma unroll
    for (int mt = 0; mt < 4; mt++) {
        const int mrow = tm * BM + wm * 64 + mt * 16 + r0;
        float* orow = out + (size_t)mrow * NTOT;
#pragma unroll
        for (int nt = 0; nt < 4; nt++) {
            const int ncol = tn * BN + wn * 32 + nt * 8 + c0;
            if (ncol + 1 < NTOT) {
                const float b0 = __ldg(bias + ncol);
                const float b1 = __ldg(bias + ncol + 1);
                float2 v0, v1;
                v0.x = fmaf(s, acc[mt][nt][0], b0);
                v0.y = fmaf(s, acc[mt][nt][1], b1);
                v1.x = fmaf(s, acc[mt][nt][2], b0);
                v1.y = fmaf(s, acc[mt][nt][3], b1);
                *reinterpret_cast<float2*>(orow + ncol) = v0;
                *reinterpret_cast<float2*>(orow + 8 * (size_t)NTOT + ncol) = v1;
            }
        }
    }
}

// ============================================================================
// Launch
// ============================================================================
extern "C" void kernel_launch(void* const* d_in, const int* in_sizes, int n_in,
                              void* d_out, int out_size) {
    const float* x     = (const float*)d_in[0];
    const int*   w     = (const int*)  d_in[1];
    const float* scale = (const float*)d_in[2];
    const float* bias  = (const float*)d_in[3];
    float* out = (float*)d_out;

    cudaFuncSetAttribute(gemm_kernel,
                         cudaFuncAttributeMaxDynamicSharedMemorySize, SMEM_TOTAL);

    convert_x_kernel<<<((size_t)MTOT * KTOT / 8) / 256, 256>>>(x);
    convert_w_kernel<<<((size_t)NTOT * KTOT / 8) / 256, 256>>>(w);
    gemm_kernel<<<NTM * NTN, NTHREADS, SMEM_TOTAL>>>(scale, bias, out);
}

// round 10
// speedup vs baseline: 1.3009x; 1.3009x over previous
#include <cuda_runtime.h>
#include <cuda_fp16.h>
#include <cstdint>

// ============================================================================
// Problem dims: out[M,N] = scale * x[M,K] @ W[N,K]^T + bias[N]
// ============================================================================
#define KTOT 4096
#define MTOT 8192   // 4 * 2048
#define NTOT 11008

constexpr int BM = 128, BN = 128, BK = 64;
constexpr int KCHUNKS = KTOT / BK;     // 64
constexpr int NTM = MTOT / BM;         // 64
constexpr int NTN = NTOT / BN;         // 86
constexpr int NSTAGE = 3;
constexpr int NTHREADS = 256;          // 8 warps, warp grid 2(M) x 4(N), tile 64x32

constexpr int A_BYTES = BM * BK * 2;            // 16384
constexpr int B_BYTES = BN * BK * 2;            // 16384
constexpr int STAGE_BYTES = A_BYTES + B_BYTES;  // 32768
constexpr int SMEM_TOTAL = NSTAGE * STAGE_BYTES;// 98304 per CTA -> 2 CTAs/SM

// ============================================================================
// Device scratch (no cudaMalloc allowed)
// ============================================================================
static __device__ __half g_xh[(size_t)MTOT * KTOT];   // 64 MB
static __device__ __half g_wh[(size_t)NTOT * KTOT];   // 86 MB

// ============================================================================
// Helpers (plain sm_103 PTX only: cp.async / ldmatrix / mma.sync)
// ============================================================================
__device__ __forceinline__ uint32_t smem_u32(const void* p) {
    return (uint32_t)__cvta_generic_to_shared(p);
}

__device__ __forceinline__ uint32_t sw128(uint32_t o) {
    return o ^ ((o >> 3) & 0x70);
}

__device__ __forceinline__ void cp16(uint32_t dst, const void* src) {
    asm volatile("cp.async.cg.shared.global [%0], [%1], 16;\n"
                 :: "r"(dst), "l"(src) : "memory");
}
#define CP_COMMIT() asm volatile("cp.async.commit_group;\n" ::: "memory")
#define CP_WAIT(N)  asm volatile("cp.async.wait_group %0;\n" :: "n"(N) : "memory")

__device__ __forceinline__ void ldsm4(uint32_t r[4], uint32_t addr) {
    asm volatile("ldmatrix.sync.aligned.m8n8.x4.shared.b16 {%0,%1,%2,%3}, [%4];"
                 : "=r"(r[0]), "=r"(r[1]), "=r"(r[2]), "=r"(r[3]) : "r"(addr));
}

__device__ __forceinline__ void mma16816(float c[4], const uint32_t a[4],
                                         uint32_t b0, uint32_t b1) {
    asm volatile(
        "mma.sync.aligned.m16n8k16.row.col.f32.f16.f16.f32 "
        "{%0,%1,%2,%3}, {%4,%5,%6,%7}, {%8,%9}, {%0,%1,%2,%3};"
        : "+f"(c[0]), "+f"(c[1]), "+f"(c[2]), "+f"(c[3])
        : "r"(a[0]), "r"(a[1]), "r"(a[2]), "r"(a[3]), "r"(b0), "r"(b1));
}

__device__ __forceinline__ uint32_t pack2(__half2 h) {
    uint32_t u;
    *reinterpret_cast<__half2*>(&u) = h;
    return u;
}

// ============================================================================
// Conversion kernels (8 elements / thread)
// ============================================================================
__global__ void __launch_bounds__(256) convert_x_kernel(const float* __restrict__ x) {
    size_t i = (size_t)blockIdx.x * 256 + threadIdx.x;
    const float4 a = reinterpret_cast<const float4*>(x)[2 * i];
    const float4 b = reinterpret_cast<const float4*>(x)[2 * i + 1];
    uint4 u;
    u.x = pack2(__floats2half2_rn(a.x, a.y));
    u.y = pack2(__floats2half2_rn(a.z, a.w));
    u.z = pack2(__floats2half2_rn(b.x, b.y));
    u.w = pack2(__floats2half2_rn(b.z, b.w));
    reinterpret_cast<uint4*>(g_xh)[i] = u;
}

__global__ void __launch_bounds__(256) convert_w_kernel(const int* __restrict__ w) {
    size_t i = (size_t)blockIdx.x * 256 + threadIdx.x;
    const int4 a = reinterpret_cast<const int4*>(w)[2 * i];
    const int4 b = reinterpret_cast<const int4*>(w)[2 * i + 1];
    uint4 u;
    u.x = pack2(__floats2half2_rn((float)a.x, (float)a.y));
    u.y = pack2(__floats2half2_rn((float)a.z, (float)a.w));
    u.z = pack2(__floats2half2_rn((float)b.x, (float)b.y));
    u.w = pack2(__floats2half2_rn((float)b.z, (float)b.w));
    reinterpret_cast<uint4*>(g_wh)[i] = u;
}

// ============================================================================
// GEMM: 256 threads, 2 CTAs/SM (16 warps/SM). Warp grid 2(M) x 4(N),
// warp tile 64x32. 3-stage cp.async pipeline with:
//   - rolling stage base pointers (no % in the loop)
//   - cp.async issue split across ks=0 (A half) and ks=1 (B half + commit)
//     so the LSU burst interleaves with MMA issue instead of colliding
//     with the first LDSM wave after the barrier.
// ============================================================================
__global__ void __launch_bounds__(NTHREADS, 2)
gemm_kernel(const float* __restrict__ scale_p, const float* __restrict__ bias,
            float* __restrict__ out)
{
    extern __shared__ char smem[];
    const uint32_t sb = smem_u32(smem);
    const int tid = threadIdx.x;
    const int wid = tid >> 5;
    const int lane = tid & 31;
    const int wm = wid & 1;        // 0..1  (M)
    const int wn = wid >> 1;       // 0..3  (N)

    // CTA rasterization: group of 16 M-tiles per N sweep (L2 reuse on B)
    const int GROUP = 16;
    const int tpg = GROUP * NTN;
    const int b = blockIdx.x;
    const int g = b / tpg;
    const int rem = b - g * tpg;
    const int tm = g * GROUP + (rem % GROUP);
    const int tn = rem / GROUP;

    const __half* xa = g_xh + (size_t)tm * BM * KTOT;
    const __half* wb = g_wh + (size_t)tn * BN * KTOT;

    // per-thread gmem base offsets for the loader (row/col fixed per thread)
    const int lrowA = tid >> 3;                  // 0..31 step over 4 iters
    const int lcol  = (tid & 7) * 8;
    const __half* xa_t = xa + (size_t)lrowA * KTOT + lcol;   // + r*32*KTOT
    const __half* wb_t = wb + (size_t)lrowA * KTOT + lcol;

    float acc[4][4][4];
#pragma unroll
    for (int mt = 0; mt < 4; mt++)
#pragma unroll
        for (int nt = 0; nt < 4; nt++)
#pragma unroll
            for (int q = 0; q < 4; q++) acc[mt][nt][q] = 0.f;

    // swizzled per-thread smem store offsets (stage-relative, constant)
    uint32_t stoff[4];
#pragma unroll
    for (int r = 0; r < 4; r++) stoff[r] = sw128((tid + r * NTHREADS) * 16);

    auto issueA = [&](uint32_t stage_base, int chunk) {
#pragma unroll
        for (int r = 0; r < 4; r++)
            cp16(stage_base + stoff[r],
                 xa_t + (size_t)(r * 32) * KTOT + chunk * BK);
    };
    auto issueB = [&](uint32_t stage_base, int chunk) {
#pragma unroll
        for (int r = 0; r < 4; r++)
            cp16(stage_base + A_BYTES + stoff[r],
                 wb_t + (size_t)(r * 32) * KTOT + chunk * BK);
        CP_COMMIT();
    };

    const uint32_t base0 = sb;
    const uint32_t base1 = sb + STAGE_BYTES;
    const uint32_t base2 = sb + 2 * STAGE_BYTES;

    issueA(base0, 0); issueB(base0, 0);
    issueA(base1, 1); issueB(base1, 1);

    // fragment double buffers
    uint32_t bfb[2][2][4];
    uint32_t afb[2][4];

    const uint32_t lrow = (uint32_t)(lane & 15) * 128;
    const uint32_t lk   = (uint32_t)(lane >> 4) * 16;   // bytes

    uint32_t cur = base0;          // stage holding chunk i
    uint32_t ldb = base2;          // freed stage -> receives chunk i+2

    for (int i = 0; i < KCHUNKS; i++) {
        if (i + 1 < KCHUNKS) { CP_WAIT(1); } else { CP_WAIT(0); }
        __syncthreads();

        const uint32_t abase = cur;
        const uint32_t bbase = cur + A_BYTES;
        const bool prefetch = (i + 2 < KCHUNKS);

        auto ldA = [&](int buf, int ks, int mt) {
            uint32_t o = (uint32_t)(wm * 64 + mt * 16) * 128 + lrow
                       + (uint32_t)ks * 32 + lk;
            ldsm4(afb[buf], abase + sw128(o));
        };
        auto ldB = [&](int buf, int ks) {
#pragma unroll
            for (int gN = 0; gN < 2; gN++) {
                uint32_t o = (uint32_t)(wn * 32 + gN * 16) * 128 + lrow
                           + (uint32_t)ks * 32 + lk;
                ldsm4(bfb[buf][gN], bbase + sw128(o));
            }
        };

        ldB(0, 0);
        ldA(0, 0, 0);

#pragma unroll
        for (int ks = 0; ks < 4; ks++) {
            if (ks < 3) ldB((ks + 1) & 1, ks + 1);
            // interleave next-chunk global loads with the MMA stream
            if (ks == 0 && prefetch) issueA(ldb, i + 2);
            if (ks == 1 && prefetch) issueB(ldb, i + 2);
#pragma unroll
            for (int mt = 0; mt < 4; mt++) {
                const int p = ks * 4 + mt;
                if (mt < 3)           ldA((p + 1) & 1, ks, mt + 1);
                else if (ks < 3)      ldA((p + 1) & 1, ks + 1, 0);
                const uint32_t* af = afb[p & 1];
                const uint32_t (*bf)[4] = bfb[ks & 1];
#pragma unroll
                for (int gN = 0; gN < 2; gN++) {
                    mma16816(acc[mt][2 * gN],     af, bf[gN][0], bf[gN][2]);
                    mma16816(acc[mt][2 * gN + 1], af, bf[gN][1], bf[gN][3]);
                }
            }
        }

        // roll stages: freed stage = cur; next cur = old cur+1
        ldb = cur;
        cur = (cur == base2) ? base0 : cur + STAGE_BYTES;
    }

    // ---- epilogue: scale * acc + bias ----
    const float s = __ldg(scale_p);
    const int r0 = lane >> 2;
    const int c0 = (lane & 3) * 2;

#pragma unroll
    for (int mt = 0; mt < 4; mt++) {
        const int mrow = tm * BM + wm * 64 + mt * 16 + r0;
        float* orow = out + (size_t)mrow * NTOT;
#pragma unroll
        for (int nt = 0; nt < 4; nt++) {
            const int ncol = tn * BN + wn * 32 + nt * 8 + c0;
            const float b0 = __ldg(bias + ncol);
            const float b1 = __ldg(bias + ncol + 1);
            float2 v0, v1;
            v0.x = fmaf(s, acc[mt][nt][0], b0);
            v0.y = fmaf(s, acc[mt][nt][1], b1);
            v1.x = fmaf(s, acc[mt][nt][2], b0);
            v1.y = fmaf(s, acc[mt][nt][3], b1);
            *reinterpret_cast<float2*>(orow + ncol) = v0;
            *reinterpret_cast<float2*>(orow + 8 * (size_t)NTOT + ncol) = v1;
        }
    }
}

// ============================================================================
// Launch
// ============================================================================
extern "C" void kernel_launch(void* const* d_in, const int* in_sizes, int n_in,
                              void* d_out, int out_size) {
    const float* x     = (const float*)d_in[0];
    const int*   w     = (const int*)  d_in[1];
    const float* scale = (const float*)d_in[2];
    const float* bias  = (const float*)d_in[3];
    float* out = (float*)d_out;

    cudaFuncSetAttribute(gemm_kernel,
                         cudaFuncAttributeMaxDynamicSharedMemorySize, SMEM_TOTAL);

    convert_x_kernel<<<((size_t)MTOT * KTOT / 8) / 256, 256>>>(x);
    convert_w_kernel<<<((size_t)NTOT * KTOT / 8) / 256, 256>>>(w);
    gemm_kernel<<<NTM * NTN, NTHREADS, SMEM_TOTAL>>>(scale, bias, out);
}

// round 11
// speedup vs baseline: 1.4006x; 1.0767x over previous
#include <cuda_runtime.h>
#include <cuda_fp16.h>
#include <cstdint>

// ============================================================================
// Problem dims: out[M,N] = scale * x[M,K] @ W[N,K]^T + bias[N]
// ============================================================================
#define KTOT 4096
#define MTOT 8192   // 4 * 2048
#define NTOT 11008

constexpr int BM = 128, BN = 128, BK = 64;
constexpr int KCHUNKS = KTOT / BK;     // 64
constexpr int NTM = MTOT / BM;         // 64
constexpr int NTN = NTOT / BN;         // 86
constexpr int NSTAGE = 3;
constexpr int NTHREADS = 256;          // 8 warps, warp grid 2(M) x 4(N), tile 64x32

constexpr int A_BYTES = BM * BK * 2;            // 16384
constexpr int B_BYTES = BN * BK * 2;            // 16384
constexpr int STAGE_BYTES = A_BYTES + B_BYTES;  // 32768
constexpr int SMEM_TOTAL = NSTAGE * STAGE_BYTES;// 98304 per CTA -> 2 CTAs/SM

// ============================================================================
// Device scratch (no cudaMalloc allowed)
// ============================================================================
static __device__ __half g_xh[(size_t)MTOT * KTOT];   // 64 MB
static __device__ __half g_wh[(size_t)NTOT * KTOT];   // 86 MB

// ============================================================================
// Helpers (plain sm_103 PTX only: cp.async / ldmatrix / mma.sync)
// ============================================================================
__device__ __forceinline__ uint32_t smem_u32(const void* p) {
    return (uint32_t)__cvta_generic_to_shared(p);
}

__device__ __forceinline__ uint32_t sw128(uint32_t o) {
    return o ^ ((o >> 3) & 0x70);
}

__device__ __forceinline__ void cp16(uint32_t dst, const void* src) {
    asm volatile("cp.async.cg.shared.global [%0], [%1], 16;\n"
                 :: "r"(dst), "l"(src) : "memory");
}
#define CP_COMMIT() asm volatile("cp.async.commit_group;\n" ::: "memory")
#define CP_WAIT(N)  asm volatile("cp.async.wait_group %0;\n" :: "n"(N) : "memory")

__device__ __forceinline__ void ldsm4(uint32_t r[4], uint32_t addr) {
    asm volatile("ldmatrix.sync.aligned.m8n8.x4.shared.b16 {%0,%1,%2,%3}, [%4];"
                 : "=r"(r[0]), "=r"(r[1]), "=r"(r[2]), "=r"(r[3]) : "r"(addr));
}

__device__ __forceinline__ void mma16816(float c[4], const uint32_t a[4],
                                         uint32_t b0, uint32_t b1) {
    asm volatile(
        "mma.sync.aligned.m16n8k16.row.col.f32.f16.f16.f32 "
        "{%0,%1,%2,%3}, {%4,%5,%6,%7}, {%8,%9}, {%0,%1,%2,%3};"
        : "+f"(c[0]), "+f"(c[1]), "+f"(c[2]), "+f"(c[3])
        : "r"(a[0]), "r"(a[1]), "r"(a[2]), "r"(a[3]), "r"(b0), "r"(b1));
}

__device__ __forceinline__ uint32_t pack2(__half2 h) {
    uint32_t u;
    *reinterpret_cast<__half2*>(&u) = h;
    return u;
}

// ============================================================================
// Conversion kernels (8 elements / thread)
// ============================================================================
__global__ void __launch_bounds__(256) convert_x_kernel(const float* __restrict__ x) {
    size_t i = (size_t)blockIdx.x * 256 + threadIdx.x;
    const float4 a = reinterpret_cast<const float4*>(x)[2 * i];
    const float4 b = reinterpret_cast<const float4*>(x)[2 * i + 1];
    uint4 u;
    u.x = pack2(__floats2half2_rn(a.x, a.y));
    u.y = pack2(__floats2half2_rn(a.z, a.w));
    u.z = pack2(__floats2half2_rn(b.x, b.y));
    u.w = pack2(__floats2half2_rn(b.z, b.w));
    reinterpret_cast<uint4*>(g_xh)[i] = u;
}

__global__ void __launch_bounds__(256) convert_w_kernel(const int* __restrict__ w) {
    size_t i = (size_t)blockIdx.x * 256 + threadIdx.x;
    const int4 a = reinterpret_cast<const int4*>(w)[2 * i];
    const int4 b = reinterpret_cast<const int4*>(w)[2 * i + 1];
    uint4 u;
    u.x = pack2(__floats2half2_rn((float)a.x, (float)a.y));
    u.y = pack2(__floats2half2_rn((float)a.z, (float)a.w));
    u.z = pack2(__floats2half2_rn((float)b.x, (float)b.y));
    u.w = pack2(__floats2half2_rn((float)b.z, (float)b.w));
    reinterpret_cast<uint4*>(g_wh)[i] = u;
}

// ============================================================================
// GEMM: 256 threads, 2 CTAs/SM. Warp grid 2(M) x 4(N), warp tile 64x32.
// R5 schedule, with ONE change: the chunk-head fragment priming LDSMs are
// issued BEFORE the 16-instruction cp.async burst, so the first MMA's
// operands don't queue behind the LDGSTS burst in the MIO pipe.
// ============================================================================
__global__ void __launch_bounds__(NTHREADS, 2)
gemm_kernel(const float* __restrict__ scale_p, const float* __restrict__ bias,
            float* __restrict__ out)
{
    extern __shared__ char smem[];
    const uint32_t sb = smem_u32(smem);
    const int tid = threadIdx.x;
    const int wid = tid >> 5;
    const int lane = tid & 31;
    const int wm = wid & 1;        // 0..1  (M)
    const int wn = wid >> 1;       // 0..3  (N)

    // CTA rasterization: group of 16 M-tiles per N sweep (L2 reuse on B)
    const int GROUP = 16;
    const int tpg = GROUP * NTN;
    const int b = blockIdx.x;
    const int g = b / tpg;
    const int rem = b - g * tpg;
    const int tm = g * GROUP + (rem % GROUP);
    const int tn = rem / GROUP;

    const __half* xa = g_xh + (size_t)tm * BM * KTOT;
    const __half* wb = g_wh + (size_t)tn * BN * KTOT;

    float acc[4][4][4];
#pragma unroll
    for (int mt = 0; mt < 4; mt++)
#pragma unroll
        for (int nt = 0; nt < 4; nt++)
#pragma unroll
            for (int q = 0; q < 4; q++) acc[mt][nt][q] = 0.f;

    // ---- async loader: one commit group per chunk ----
    auto load_chunk = [&](int stage, int chunk) {
        const uint32_t st = sb + stage * STAGE_BYTES;
        const int c0 = chunk * BK;
#pragma unroll
        for (int r = 0; r < 4; r++) {        // A: 128 rows x 128B
            int u = tid + r * 256;
            int row = u >> 3, col = (u & 7) * 8;
            cp16(st + sw128(u * 16), xa + (size_t)row * KTOT + c0 + col);
        }
#pragma unroll
        for (int r = 0; r < 4; r++) {        // B: 128 rows x 128B
            int u = tid + r * 256;
            int row = u >> 3, col = (u & 7) * 8;
            cp16(st + A_BYTES + sw128(u * 16), wb + (size_t)row * KTOT + c0 + col);
        }
        CP_COMMIT();
    };

    load_chunk(0, 0);
    load_chunk(1, 1);

    // fragment double buffers
    uint32_t bfb[2][2][4];    // [buf][gN][4]
    uint32_t afb[2][4];       // [buf][4]

    const uint32_t lrow = (uint32_t)(lane & 15) * 128;
    const uint32_t lk   = (uint32_t)(lane >> 4) * 16;   // bytes

    for (int i = 0; i < KCHUNKS; i++) {
        const int st = i % NSTAGE;
        if (i + 1 < KCHUNKS) { CP_WAIT(1); } else { CP_WAIT(0); }
        __syncthreads();

        const uint32_t abase = sb + st * STAGE_BYTES;
        const uint32_t bbase = abase + A_BYTES;

        auto ldA = [&](int buf, int ks, int mt) {
            uint32_t o = (uint32_t)(wm * 64 + mt * 16) * 128 + lrow
                       + (uint32_t)ks * 32 + lk;
            ldsm4(afb[buf], abase + sw128(o));
        };
        auto ldB = [&](int buf, int ks) {
#pragma unroll
            for (int gN = 0; gN < 2; gN++) {
                uint32_t o = (uint32_t)(wn * 32 + gN * 16) * 128 + lrow
                           + (uint32_t)ks * 32 + lk;
                ldsm4(bfb[buf][gN], bbase + sw128(o));
            }
        };

        // prime the register pipeline FIRST (critical path for first MMA),
        // THEN issue the next chunk's cp.async burst.
        ldB(0, 0);
        ldA(0, 0, 0);
        if (i + 2 < KCHUNKS) load_chunk((i + 2) % NSTAGE, i + 2);

#pragma unroll
        for (int ks = 0; ks < 4; ks++) {
            if (ks < 3) ldB((ks + 1) & 1, ks + 1);
#pragma unroll
            for (int mt = 0; mt < 4; mt++) {
                const int p = ks * 4 + mt;
                if (mt < 3)           ldA((p + 1) & 1, ks, mt + 1);
                else if (ks < 3)      ldA((p + 1) & 1, ks + 1, 0);
                const uint32_t* af = afb[p & 1];
                const uint32_t (*bf)[4] = bfb[ks & 1];
#pragma unroll
                for (int gN = 0; gN < 2; gN++) {
                    mma16816(acc[mt][2 * gN],     af, bf[gN][0], bf[gN][2]);
                    mma16816(acc[mt][2 * gN + 1], af, bf[gN][1], bf[gN][3]);
                }
            }
        }
    }

    // ---- epilogue: scale * acc + bias ----
    const float s = __ldg(scale_p);
    const int r0 = lane >> 2;
    const int c0 = (lane & 3) * 2;

#pragma unroll
    for (int mt = 0; mt < 4; mt++) {
        const int mrow = tm * BM + wm * 64 + mt * 16 + r0;
        float* orow = out + (size_t)mrow * NTOT;
#pragma unroll
        for (int nt = 0; nt < 4; nt++) {
            const int ncol = tn * BN + wn * 32 + nt * 8 + c0;
            const float b0 = __ldg(bias + ncol);
            const float b1 = __ldg(bias + ncol + 1);
            float2 v0, v1;
            v0.x = fmaf(s, acc[mt][nt][0], b0);
            v0.y = fmaf(s, acc[mt][nt][1], b1);
            v1.x = fmaf(s, acc[mt][nt][2], b0);
            v1.y = fmaf(s, acc[mt][nt][3], b1);
            *reinterpret_cast<float2*>(orow + ncol) = v0;
            *reinterpret_cast<float2*>(orow + 8 * (size_t)NTOT + ncol) = v1;
        }
    }
}

// ============================================================================
// Launch
// ============================================================================
extern "C" void kernel_launch(void* const* d_in, const int* in_sizes, int n_in,
                              void* d_out, int out_size) {
    const float* x     = (const float*)d_in[0];
    const int*   w     = (const int*)  d_in[1];
    const float* scale = (const float*)d_in[2];
    const float* bias  = (const float*)d_in[3];
    float* out = (float*)d_out;

    cudaFuncSetAttribute(gemm_kernel,
                         cudaFuncAttributeMaxDynamicSharedMemorySize, SMEM_TOTAL);

    convert_x_kernel<<<((size_t)MTOT * KTOT / 8) / 256, 256>>>(x);
    convert_w_kernel<<<((size_t)NTOT * KTOT / 8) / 256, 256>>>(w);
    gemm_kernel<<<NTM * NTN, NTHREADS, SMEM_TOTAL>>>(scale, bias, out);
}

// round 12
// speedup vs baseline: 1.4797x; 1.0564x over previous
#include <cuda_runtime.h>
#include <cuda_fp16.h>
#include <cstdint>

// ============================================================================
// Problem dims: out[M,N] = scale * x[M,K] @ W[N,K]^T + bias[N]
// ============================================================================
#define KTOT 4096
#define MTOT 8192   // 4 * 2048
#define NTOT 11008

constexpr int BM = 128, BN = 128, BK = 64;
constexpr int KCHUNKS = KTOT / BK;     // 64
constexpr int NTM = MTOT / BM;         // 64
constexpr int NTN = NTOT / BN;         // 86
constexpr int NSTAGE = 4;
constexpr int NTHREADS = 256;          // 8 warps, warp grid 2(M) x 4(N), tile 64x32

constexpr int A_BYTES = BM * BK * 2;            // 16384 (fp16)
constexpr int B_BYTES = BN * BK;                // 8192  (int8!)
constexpr int STAGE_BYTES = A_BYTES + B_BYTES;  // 24576 (1024-aligned)
constexpr int SMEM_TOTAL = NSTAGE * STAGE_BYTES;// 98304 per CTA -> 2 CTAs/SM

// ============================================================================
// Device scratch (no cudaMalloc allowed)
// g_xh holds x in fp16 with a within-16 k-permutation (see convert_x);
// g_wb holds W packed to int8, natural k order.
// The permutation compensates the int8 ldmatrix fragment byte layout, and is
// applied identically to both GEMM operands => dot product unchanged.
// ============================================================================
static __device__ __half  g_xh[(size_t)MTOT * KTOT];   // 64 MB
static __device__ int8_t  g_wb[(size_t)NTOT * KTOT];   // 43 MB

// ============================================================================
// Helpers (plain sm_103 PTX only: cp.async / ldmatrix / mma.sync)
// ============================================================================
__device__ __forceinline__ uint32_t smem_u32(const void* p) {
    return (uint32_t)__cvta_generic_to_shared(p);
}

__device__ __forceinline__ uint32_t sw128(uint32_t o) {
    return o ^ ((o >> 3) & 0x70);
}

__device__ __forceinline__ void cp16(uint32_t dst, const void* src) {
    asm volatile("cp.async.cg.shared.global [%0], [%1], 16;\n"
                 :: "r"(dst), "l"(src) : "memory");
}
#define CP_COMMIT() asm volatile("cp.async.commit_group;\n" ::: "memory")
#define CP_WAIT(N)  asm volatile("cp.async.wait_group %0;\n" :: "n"(N) : "memory")

__device__ __forceinline__ void ldsm4(uint32_t r[4], uint32_t addr) {
    asm volatile("ldmatrix.sync.aligned.m8n8.x4.shared.b16 {%0,%1,%2,%3}, [%4];"
                 : "=r"(r[0]), "=r"(r[1]), "=r"(r[2]), "=r"(r[3]) : "r"(addr));
}

__device__ __forceinline__ void mma16816(float c[4], const uint32_t a[4],
                                         uint32_t b0, uint32_t b1) {
    asm volatile(
        "mma.sync.aligned.m16n8k16.row.col.f32.f16.f16.f32 "
        "{%0,%1,%2,%3}, {%4,%5,%6,%7}, {%8,%9}, {%0,%1,%2,%3};"
        : "+f"(c[0]), "+f"(c[1]), "+f"(c[2]), "+f"(c[3])
        : "r"(a[0]), "r"(a[1]), "r"(a[2]), "r"(a[3]), "r"(b0), "r"(b1));
}

// int8x4 (signed) -> two fp16x2 regs, exact. 5 ops, ALU/FMA pipes (idle here).
__device__ __forceinline__ void unpack_b(uint32_t r, uint32_t& b0, uint32_t& b1) {
    uint32_t t = r ^ 0x80808080u;       // signed -> offset-binary
    uint32_t h01, h23;
    asm("prmt.b32 %0, %1, %2, 0x4140;" : "=r"(h01) : "r"(t), "r"(0x64646464u));
    asm("prmt.b32 %0, %1, %2, 0x4342;" : "=r"(h23) : "r"(t), "r"(0x64646464u));
    asm("sub.f16x2 %0, %1, %2;" : "=r"(b0) : "r"(h01), "r"(0x64806480u)); // -1152
    asm("sub.f16x2 %0, %1, %2;" : "=r"(b1) : "r"(h23), "r"(0x64806480u));
}

__device__ __forceinline__ uint32_t pack2(__half2 h) {
    uint32_t u;
    *reinterpret_cast<__half2*>(&u) = h;
    return u;
}

// ============================================================================
// Conversion kernels
// ============================================================================
// x -> fp16 with within-16 k-shuffle:
//   new pos 2c+j      <- old k 4c+j      (c=0..3, j=0..1)
//   new pos 8+2c+j    <- old k 4c+2+j
// One thread = one 16-k block (64B read, 32B write).
__global__ void __launch_bounds__(256) convert_x_kernel(const float* __restrict__ x) {
    size_t i = (size_t)blockIdx.x * 256 + threadIdx.x;
    const float4 f0 = reinterpret_cast<const float4*>(x)[4 * i + 0]; // k 0-3
    const float4 f1 = reinterpret_cast<const float4*>(x)[4 * i + 1]; // k 4-7
    const float4 f2 = reinterpret_cast<const float4*>(x)[4 * i + 2]; // k 8-11
    const float4 f3 = reinterpret_cast<const float4*>(x)[4 * i + 3]; // k 12-15
    uint4 u0, u1;
    u0.x = pack2(__floats2half2_rn(f0.x, f0.y));   // pos 0,1   <- k 0,1
    u0.y = pack2(__floats2half2_rn(f1.x, f1.y));   // pos 2,3   <- k 4,5
    u0.z = pack2(__floats2half2_rn(f2.x, f2.y));   // pos 4,5   <- k 8,9
    u0.w = pack2(__floats2half2_rn(f3.x, f3.y));   // pos 6,7   <- k 12,13
    u1.x = pack2(__floats2half2_rn(f0.z, f0.w));   // pos 8,9   <- k 2,3
    u1.y = pack2(__floats2half2_rn(f1.z, f1.w));   // pos 10,11 <- k 6,7
    u1.z = pack2(__floats2half2_rn(f2.z, f2.w));   // pos 12,13 <- k 10,11
    u1.w = pack2(__floats2half2_rn(f3.z, f3.w));   // pos 14,15 <- k 14,15
    reinterpret_cast<uint4*>(g_xh)[2 * i + 0] = u0;
    reinterpret_cast<uint4*>(g_xh)[2 * i + 1] = u1;
}

// W int32 -> packed int8 (natural k order). One thread = 16 values.
__global__ void __launch_bounds__(256) pack_w_kernel(const int* __restrict__ w) {
    size_t i = (size_t)blockIdx.x * 256 + threadIdx.x;
    const int4 a = reinterpret_cast<const int4*>(w)[4 * i + 0];
    const int4 b = reinterpret_cast<const int4*>(w)[4 * i + 1];
    const int4 c = reinterpret_cast<const int4*>(w)[4 * i + 2];
    const int4 d = reinterpret_cast<const int4*>(w)[4 * i + 3];
    uint4 u;
    u.x = (a.x & 0xFF) | ((a.y & 0xFF) << 8) | ((a.z & 0xFF) << 16) | ((uint32_t)a.w << 24);
    u.y = (b.x & 0xFF) | ((b.y & 0xFF) << 8) | ((b.z & 0xFF) << 16) | ((uint32_t)b.w << 24);
    u.z = (c.x & 0xFF) | ((c.y & 0xFF) << 8) | ((c.z & 0xFF) << 16) | ((uint32_t)c.w << 24);
    u.w = (d.x & 0xFF) | ((d.y & 0xFF) << 8) | ((d.z & 0xFF) << 16) | ((uint32_t)d.w << 24);
    reinterpret_cast<uint4*>(g_wb)[i] = u;
}

// ============================================================================
// GEMM: 256 threads, 2 CTAs/SM (16 warps/SM). Warp grid 2(M) x 4(N),
// warp tile 64x32. B kept int8 in SMEM (8KB/stage): one ldmatrix.x4 covers
// n16 x k32; fragments expanded to fp16 in registers. 4-stage cp.async pipe.
// B SMEM layout: 64 rows x 128B; row j holds n=2j (64B) ++ n=2j+1 (64B), SW128.
// ============================================================================
__global__ void __launch_bounds__(NTHREADS, 2)
gemm_kernel(const float* __restrict__ scale_p, const float* __restrict__ bias,
            float* __restrict__ out)
{
    extern __shared__ char smem[];
    const uint32_t sb = smem_u32(smem);
    const int tid = threadIdx.x;
    const int wid = tid >> 5;
    const int lane = tid & 31;
    const int wm = wid & 1;        // 0..1  (M)
    const int wn = wid >> 1;       // 0..3  (N)

    // CTA rasterization: group of 16 M-tiles per N sweep (L2 reuse on B)
    const int GROUP = 16;
    const int tpg = GROUP * NTN;
    const int b = blockIdx.x;
    const int g = b / tpg;
    const int rem = b - g * tpg;
    const int tm = g * GROUP + (rem % GROUP);
    const int tn = rem / GROUP;

    const __half*  xa = g_xh + (size_t)tm * BM * KTOT;
    const int8_t*  wb = g_wb + (size_t)tn * BN * KTOT;

    float acc[4][4][4];
#pragma unroll
    for (int mt = 0; mt < 4; mt++)
#pragma unroll
        for (int nt = 0; nt < 4; nt++)
#pragma unroll
            for (int q = 0; q < 4; q++) acc[mt][nt][q] = 0.f;

    // ---- async loader: A 1024 16B-units fp16, B 512 16B-units int8 ----
    auto load_chunk = [&](int stage, int chunk) {
        const uint32_t st = sb + stage * STAGE_BYTES;
        const int c0 = chunk * BK;
#pragma unroll
        for (int r = 0; r < 4; r++) {        // A: 128 rows x 128B
            int u = tid + r * 256;
            int row = u >> 3, col = (u & 7) * 8;
            cp16(st + sw128(u * 16), xa + (size_t)row * KTOT + c0 + col);
        }
#pragma unroll
        for (int r = 0; r < 2; r++) {        // B: 128 n-rows x 64B int8
            int u = tid + r * 256;
            int n = u >> 2, ksel = u & 3;
            uint32_t doff = (uint32_t)(n >> 1) * 128 + (n & 1) * 64 + ksel * 16;
            cp16(st + A_BYTES + sw128(doff), wb + (size_t)n * KTOT + c0 + ksel * 16);
        }
        CP_COMMIT();
    };

    load_chunk(0, 0);
    load_chunk(1, 1);
    load_chunk(2, 2);

    // fragment buffers
    uint32_t braw[2][2][4];   // [ks2][gN][mat]: mats = {n-lo s0, n-hi s0, n-lo s1, n-hi s1}
    uint32_t afb[2][4];       // A double buffer (R5 scheme)

    const uint32_t lrow = (uint32_t)(lane & 15) * 128;
    const uint32_t lk   = (uint32_t)(lane >> 4) * 16;   // bytes

    for (int i = 0; i < KCHUNKS; i++) {
        const int st = i & 3;
        if (i + 2 < KCHUNKS)      { CP_WAIT(2); }
        else if (i + 1 < KCHUNKS) { CP_WAIT(1); }
        else                      { CP_WAIT(0); }
        __syncthreads();

        const uint32_t abase = sb + st * STAGE_BYTES;
        const uint32_t bbase = abase + A_BYTES;

        auto ldA = [&](int buf, int ks, int mt) {
            uint32_t o = (uint32_t)(wm * 64 + mt * 16) * 128 + lrow
                       + (uint32_t)ks * 32 + lk;
            ldsm4(afb[buf], abase + sw128(o));
        };
        // one ldsm4 per gN covers n16 x k32 (two k16 steps)
        auto ldB2 = [&](int ks2) {
#pragma unroll
            for (int gN = 0; gN < 2; gN++) {
                uint32_t n_loc = (uint32_t)(wn * 32 + gN * 16) + (lane & 15);
                uint32_t o = (n_loc >> 1) * 128 + (n_loc & 1) * 64
                           + (uint32_t)ks2 * 32 + lk;
                ldsm4(braw[ks2][gN], bbase + sw128(o));
            }
        };

        ldB2(0);
        ldA(0, 0, 0);
        if (i + 3 < KCHUNKS) load_chunk((i + 3) & 3, i + 3);
        ldB2(1);

#pragma unroll
        for (int ks = 0; ks < 4; ks++) {
            const int ks2 = ks >> 1, sub = ks & 1;
            // expand this k16 step's B fragments: int8x4 -> fp16x2 pairs
            uint32_t ub[2][4];
#pragma unroll
            for (int gN = 0; gN < 2; gN++) {
                unpack_b(braw[ks2][gN][2 * sub + 0], ub[gN][0], ub[gN][1]); // n-lo b0,b1
                unpack_b(braw[ks2][gN][2 * sub + 1], ub[gN][2], ub[gN][3]); // n-hi b0,b1
            }
#pragma unroll
            for (int mt = 0; mt < 4; mt++) {
                const int p = ks * 4 + mt;
                if (mt < 3)           ldA((p + 1) & 1, ks, mt + 1);
                else if (ks < 3)      ldA((p + 1) & 1, ks + 1, 0);
                const uint32_t* af = afb[p & 1];
#pragma unroll
                for (int gN = 0; gN < 2; gN++) {
                    mma16816(acc[mt][2 * gN],     af, ub[gN][0], ub[gN][1]);
                    mma16816(acc[mt][2 * gN + 1], af, ub[gN][2], ub[gN][3]);
                }
            }
        }
    }

    // ---- epilogue: scale * acc + bias ----
    const float s = __ldg(scale_p);
    const int r0 = lane >> 2;
    const int c0 = (lane & 3) * 2;

#pragma unroll
    for (int mt = 0; mt < 4; mt++) {
        const int mrow = tm * BM + wm * 64 + mt * 16 + r0;
        float* orow = out + (size_t)mrow * NTOT;
#pragma unroll
        for (int nt = 0; nt < 4; nt++) {
            const int ncol = tn * BN + wn * 32 + nt * 8 + c0;
            const float b0 = __ldg(bias + ncol);
            const float b1 = __ldg(bias + ncol + 1);
            float2 v0, v1;
            v0.x = fmaf(s, acc[mt][nt][0], b0);
            v0.y = fmaf(s, acc[mt][nt][1], b1);
            v1.x = fmaf(s, acc[mt][nt][2], b0);
            v1.y = fmaf(s, acc[mt][nt][3], b1);
            *reinterpret_cast<float2*>(orow + ncol) = v0;
            *reinterpret_cast<float2*>(orow + 8 * (size_t)NTOT + ncol) = v1;
        }
    }
}

// ============================================================================
// Launch
// ============================================================================
extern "C" void kernel_launch(void* const* d_in, const int* in_sizes, int n_in,
                              void* d_out, int out_size) {
    const float* x     = (const float*)d_in[0];
    const int*   w     = (const int*)  d_in[1];
    const float* scale = (const float*)d_in[2];
    const float* bias  = (const float*)d_in[3];
    float* out = (float*)d_out;

    cudaFuncSetAttribute(gemm_kernel,
                         cudaFuncAttributeMaxDynamicSharedMemorySize, SMEM_TOTAL);

    convert_x_kernel<<<((size_t)MTOT * KTOT / 16) / 256, 256>>>(x);
    pack_w_kernel<<<((size_t)NTOT * KTOT / 16) / 256, 256>>>(w);
    gemm_kernel<<<NTM * NTN, NTHREADS, SMEM_TOTAL>>>(scale, bias, out);
}

// round 13
// speedup vs baseline: 1.5442x; 1.0436x over previous
#include <cuda_runtime.h>
#include <cuda_fp16.h>
#include <cstdint>

// ============================================================================
// Problem dims: out[M,N] = scale * x[M,K] @ W[N,K]^T + bias[N]
// ============================================================================
#define KTOT 4096
#define MTOT 8192   // 4 * 2048
#define NTOT 11008

constexpr int BM = 128, BN = 128, BK = 64;
constexpr int KCHUNKS = KTOT / BK;     // 64
constexpr int NPAIRS = KCHUNKS / 2;    // 32
constexpr int NTM = MTOT / BM;         // 64
constexpr int NTN = NTOT / BN;         // 86
constexpr int NTHREADS = 256;          // 8 warps, warp grid 2(M) x 4(N), tile 64x32

constexpr int A_BYTES = BM * BK * 2;            // 16384 (fp16)
constexpr int B_BYTES = BN * BK;                // 8192  (int8!)
constexpr int STAGE_BYTES = A_BYTES + B_BYTES;  // 24576
constexpr int SMEM_TOTAL = 4 * STAGE_BYTES;     // 98304 per CTA -> 2 CTAs/SM

// ============================================================================
// Device scratch (no cudaMalloc allowed)
// g_xh holds x in fp16 with a within-16 k-permutation (see convert_x);
// g_wb holds W packed to int8, natural k order.
// The permutation compensates the int8 ldmatrix fragment byte layout, and is
// applied identically to both GEMM operands => dot product unchanged.
// ============================================================================
static __device__ __half  g_xh[(size_t)MTOT * KTOT];   // 64 MB
static __device__ int8_t  g_wb[(size_t)NTOT * KTOT];   // 43 MB

// ============================================================================
// Helpers (plain sm_103 PTX only: cp.async / ldmatrix / mma.sync)
// ============================================================================
__device__ __forceinline__ uint32_t smem_u32(const void* p) {
    return (uint32_t)__cvta_generic_to_shared(p);
}

__device__ __forceinline__ uint32_t sw128(uint32_t o) {
    return o ^ ((o >> 3) & 0x70);
}

__device__ __forceinline__ void cp16(uint32_t dst, const void* src) {
    asm volatile("cp.async.cg.shared.global [%0], [%1], 16;\n"
                 :: "r"(dst), "l"(src) : "memory");
}
#define CP_COMMIT() asm volatile("cp.async.commit_group;\n" ::: "memory")
#define CP_WAIT(N)  asm volatile("cp.async.wait_group %0;\n" :: "n"(N) : "memory")

__device__ __forceinline__ void ldsm4(uint32_t r[4], uint32_t addr) {
    asm volatile("ldmatrix.sync.aligned.m8n8.x4.shared.b16 {%0,%1,%2,%3}, [%4];"
                 : "=r"(r[0]), "=r"(r[1]), "=r"(r[2]), "=r"(r[3]) : "r"(addr));
}

__device__ __forceinline__ void mma16816(float c[4], const uint32_t a[4],
                                         uint32_t b0, uint32_t b1) {
    asm volatile(
        "mma.sync.aligned.m16n8k16.row.col.f32.f16.f16.f32 "
        "{%0,%1,%2,%3}, {%4,%5,%6,%7}, {%8,%9}, {%0,%1,%2,%3};"
        : "+f"(c[0]), "+f"(c[1]), "+f"(c[2]), "+f"(c[3])
        : "r"(a[0]), "r"(a[1]), "r"(a[2]), "r"(a[3]), "r"(b0), "r"(b1));
}

// int8x4 (signed) -> two fp16x2 regs, exact. 5 ops, ALU/FMA pipes.
__device__ __forceinline__ void unpack_b(uint32_t r, uint32_t& b0, uint32_t& b1) {
    uint32_t t = r ^ 0x80808080u;       // signed -> offset-binary
    uint32_t h01, h23;
    asm("prmt.b32 %0, %1, %2, 0x4140;" : "=r"(h01) : "r"(t), "r"(0x64646464u));
    asm("prmt.b32 %0, %1, %2, 0x4342;" : "=r"(h23) : "r"(t), "r"(0x64646464u));
    asm("sub.f16x2 %0, %1, %2;" : "=r"(b0) : "r"(h01), "r"(0x64806480u)); // -1152
    asm("sub.f16x2 %0, %1, %2;" : "=r"(b1) : "r"(h23), "r"(0x64806480u));
}

__device__ __forceinline__ uint32_t pack2(__half2 h) {
    uint32_t u;
    *reinterpret_cast<__half2*>(&u) = h;
    return u;
}

// ============================================================================
// Conversion kernels
// ============================================================================
// x -> fp16 with within-16 k-shuffle (compensates int8 fragment byte layout):
//   new pos 2c+j   <- old k 4c+j ;  new pos 8+2c+j <- old k 4c+2+j
__global__ void __launch_bounds__(256) convert_x_kernel(const float* __restrict__ x) {
    size_t i = (size_t)blockIdx.x * 256 + threadIdx.x;
    const float4 f0 = reinterpret_cast<const float4*>(x)[4 * i + 0]; // k 0-3
    const float4 f1 = reinterpret_cast<const float4*>(x)[4 * i + 1]; // k 4-7
    const float4 f2 = reinterpret_cast<const float4*>(x)[4 * i + 2]; // k 8-11
    const float4 f3 = reinterpret_cast<const float4*>(x)[4 * i + 3]; // k 12-15
    uint4 u0, u1;
    u0.x = pack2(__floats2half2_rn(f0.x, f0.y));
    u0.y = pack2(__floats2half2_rn(f1.x, f1.y));
    u0.z = pack2(__floats2half2_rn(f2.x, f2.y));
    u0.w = pack2(__floats2half2_rn(f3.x, f3.y));
    u1.x = pack2(__floats2half2_rn(f0.z, f0.w));
    u1.y = pack2(__floats2half2_rn(f1.z, f1.w));
    u1.z = pack2(__floats2half2_rn(f2.z, f2.w));
    u1.w = pack2(__floats2half2_rn(f3.z, f3.w));
    reinterpret_cast<uint4*>(g_xh)[2 * i + 0] = u0;
    reinterpret_cast<uint4*>(g_xh)[2 * i + 1] = u1;
}

// W int32 -> packed int8 (natural k order). One thread = 16 values.
__global__ void __launch_bounds__(256) pack_w_kernel(const int* __restrict__ w) {
    size_t i = (size_t)blockIdx.x * 256 + threadIdx.x;
    const int4 a = reinterpret_cast<const int4*>(w)[4 * i + 0];
    const int4 b = reinterpret_cast<const int4*>(w)[4 * i + 1];
    const int4 c = reinterpret_cast<const int4*>(w)[4 * i + 2];
    const int4 d = reinterpret_cast<const int4*>(w)[4 * i + 3];
    uint4 u;
    u.x = (a.x & 0xFF) | ((a.y & 0xFF) << 8) | ((a.z & 0xFF) << 16) | ((uint32_t)a.w << 24);
    u.y = (b.x & 0xFF) | ((b.y & 0xFF) << 8) | ((b.z & 0xFF) << 16) | ((uint32_t)b.w << 24);
    u.z = (c.x & 0xFF) | ((c.y & 0xFF) << 8) | ((c.z & 0xFF) << 16) | ((uint32_t)c.w << 24);
    u.w = (d.x & 0xFF) | ((d.y & 0xFF) << 8) | ((d.z & 0xFF) << 16) | ((uint32_t)d.w << 24);
    reinterpret_cast<uint4*>(g_wb)[i] = u;
}

// ============================================================================
// GEMM: 256 threads, 2 CTAs/SM (16 warps/SM). Warp grid 2(M) x 4(N),
// warp tile 64x32. B int8 in SMEM (one ldmatrix.x4 = n16 x k32), expanded to
// fp16 in registers. 4 stages, PAIR-granular sync: one CP_WAIT+__syncthreads
// per 2 chunks (32 rendezvous per tile instead of 64).
// B SMEM layout: 64 rows x 128B; row j = n=2j (64B) ++ n=2j+1 (64B), SW128.
// ============================================================================
__global__ void __launch_bounds__(NTHREADS, 2)
gemm_kernel(const float* __restrict__ scale_p, const float* __restrict__ bias,
            float* __restrict__ out)
{
    extern __shared__ char smem[];
    const uint32_t sb = smem_u32(smem);
    const int tid = threadIdx.x;
    const int wid = tid >> 5;
    const int lane = tid & 31;
    const int wm = wid & 1;        // 0..1  (M)
    const int wn = wid >> 1;       // 0..3  (N)

    // CTA rasterization: group of 16 M-tiles per N sweep (L2 reuse on B)
    const int GROUP = 16;
    const int tpg = GROUP * NTN;
    const int b = blockIdx.x;
    const int g = b / tpg;
    const int rem = b - g * tpg;
    const int tm = g * GROUP + (rem % GROUP);
    const int tn = rem / GROUP;

    const __half*  xa = g_xh + (size_t)tm * BM * KTOT;
    const int8_t*  wb = g_wb + (size_t)tn * BN * KTOT;

    float acc[4][4][4];
#pragma unroll
    for (int mt = 0; mt < 4; mt++)
#pragma unroll
        for (int nt = 0; nt < 4; nt++)
#pragma unroll
            for (int q = 0; q < 4; q++) acc[mt][nt][q] = 0.f;

    // ---- async loader for one chunk ----
    auto load_chunk = [&](int stage, int chunk) {
        const uint32_t st = sb + stage * STAGE_BYTES;
        const int c0 = chunk * BK;
#pragma unroll
        for (int r = 0; r < 4; r++) {        // A: 128 rows x 128B fp16
            int u = tid + r * 256;
            int row = u >> 3, col = (u & 7) * 8;
            cp16(st + sw128(u * 16), xa + (size_t)row * KTOT + c0 + col);
        }
#pragma unroll
        for (int r = 0; r < 2; r++) {        // B: 128 n-rows x 64B int8
            int u = tid + r * 256;
            int n = u >> 2, ksel = u & 3;
            uint32_t doff = (uint32_t)(n >> 1) * 128 + (n & 1) * 64 + ksel * 16;
            cp16(st + A_BYTES + sw128(doff), wb + (size_t)n * KTOT + c0 + ksel * 16);
        }
        CP_COMMIT();
    };

    const uint32_t lrow = (uint32_t)(lane & 15) * 128;
    const uint32_t lk   = (uint32_t)(lane >> 4) * 16;   // bytes

    // fragment buffers
    uint32_t braw[2][2][4];   // [ks2][gN][mat]
    uint32_t afb[2][4];       // A double buffer

    // ---- compute one chunk resident in stage `st` ----
    auto compute_chunk = [&](int st) {
        const uint32_t abase = sb + st * STAGE_BYTES;
        const uint32_t bbase = abase + A_BYTES;

        auto ldA = [&](int buf, int ks, int mt) {
            uint32_t o = (uint32_t)(wm * 64 + mt * 16) * 128 + lrow
                       + (uint32_t)ks * 32 + lk;
            ldsm4(afb[buf], abase + sw128(o));
        };
        auto ldB2 = [&](int ks2) {
#pragma unroll
            for (int gN = 0; gN < 2; gN++) {
                uint32_t n_loc = (uint32_t)(wn * 32 + gN * 16) + (lane & 15);
                uint32_t o = (n_loc >> 1) * 128 + (n_loc & 1) * 64
                           + (uint32_t)ks2 * 32 + lk;
                ldsm4(braw[ks2][gN], bbase + sw128(o));
            }
        };

        ldB2(0);
        ldA(0, 0, 0);
        ldB2(1);

#pragma unroll
        for (int ks = 0; ks < 4; ks++) {
            const int ks2 = ks >> 1, sub = ks & 1;
            uint32_t ub[2][4];
#pragma unroll
            for (int gN = 0; gN < 2; gN++) {
                unpack_b(braw[ks2][gN][2 * sub + 0], ub[gN][0], ub[gN][1]);
                unpack_b(braw[ks2][gN][2 * sub + 1], ub[gN][2], ub[gN][3]);
            }
#pragma unroll
            for (int mt = 0; mt < 4; mt++) {
                const int p = ks * 4 + mt;
                if (mt < 3)           ldA((p + 1) & 1, ks, mt + 1);
                else if (ks < 3)      ldA((p + 1) & 1, ks + 1, 0);
                const uint32_t* af = afb[p & 1];
#pragma unroll
                for (int gN = 0; gN < 2; gN++) {
                    mma16816(acc[mt][2 * gN],     af, ub[gN][0], ub[gN][1]);
                    mma16816(acc[mt][2 * gN + 1], af, ub[gN][2], ub[gN][3]);
                }
            }
        }
    };

    // prologue: pair 0 (chunks 0,1) into stages 0,1
    load_chunk(0, 0);
    load_chunk(1, 1);

    for (int p = 0; p < NPAIRS; p++) {
        CP_WAIT(0);            // own groups for pair p done (issued pair ago)
        __syncthreads();       // all threads' writes visible; prev-pair reads done

        // prefetch pair p+1 into the stages freed before this barrier
        if (p + 1 < NPAIRS) {
            const int c = 2 * (p + 1);
            load_chunk(c & 3, c);
            load_chunk((c + 1) & 3, c + 1);
        }

        compute_chunk((2 * p) & 3);
        compute_chunk((2 * p + 1) & 3);
    }

    // ---- epilogue: scale * acc + bias ----
    const float s = __ldg(scale_p);
    const int r0 = lane >> 2;
    const int c0 = (lane & 3) * 2;

#pragma unroll
    for (int mt = 0; mt < 4; mt++) {
        const int mrow = tm * BM + wm * 64 + mt * 16 + r0;
        float* orow = out + (size_t)mrow * NTOT;
#pragma unroll
        for (int nt = 0; nt < 4; nt++) {
            const int ncol = tn * BN + wn * 32 + nt * 8 + c0;
            const float b0 = __ldg(bias + ncol);
            const float b1 = __ldg(bias + ncol + 1);
            float2 v0, v1;
            v0.x = fmaf(s, acc[mt][nt][0], b0);
            v0.y = fmaf(s, acc[mt][nt][1], b1);
            v1.x = fmaf(s, acc[mt][nt][2], b0);
            v1.y = fmaf(s, acc[mt][nt][3], b1);
            *reinterpret_cast<float2*>(orow + ncol) = v0;
            *reinterpret_cast<float2*>(orow + 8 * (size_t)NTOT + ncol) = v1;
        }
    }
}

// ============================================================================
// Launch
// ============================================================================
extern "C" void kernel_launch(void* const* d_in, const int* in_sizes, int n_in,
                              void* d_out, int out_size) {
    const float* x     = (const float*)d_in[0];
    const int*   w     = (const int*)  d_in[1];
    const float* scale = (const float*)d_in[2];
    const float* bias  = (const float*)d_in[3];
    float* out = (float*)d_out;

    cudaFuncSetAttribute(gemm_kernel,
                         cudaFuncAttributeMaxDynamicSharedMemorySize, SMEM_TOTAL);

    convert_x_kernel<<<((size_t)MTOT * KTOT / 16) / 256, 256>>>(x);
    pack_w_kernel<<<((size_t)NTOT * KTOT / 16) / 256, 256>>>(w);
    gemm_kernel<<<NTM * NTN, NTHREADS, SMEM_TOTAL>>>(scale, bias, out);
}